// round 2
// baseline (speedup 1.0000x reference)
#include <cuda_runtime.h>
#include <cstdint>
#include <math.h>

#define LSEQ 4096
#define HDIM 512

// ---------------- scratch (__device__ globals; no allocation allowed) ----------------
__device__ float d_gi[2][(size_t)LSEQ * 1536];       // precomputed input gates, per dir
__device__ float d_hstate[2][2 * HDIM];              // double-buffered h per dir
__device__ unsigned int d_bar[2];                    // per-direction barrier counters
__device__ float d_outcat[(size_t)LSEQ * 1024];      // [out_f | out_b]
__device__ float d_U1[(size_t)LSEQ * 9216];          // KAN1 augmented input
__device__ float d_V1[(size_t)HDIM * 9216];          // KAN1 augmented weight
__device__ float d_U2[(size_t)LSEQ * 4608];          // KAN2 augmented input
__device__ float d_V2[(size_t)HDIM * 4608];          // KAN2 augmented weight
__device__ float d_a2[(size_t)LSEQ * HDIM];          // KAN2 output

// ---------------- init ----------------
__global__ void init_kernel() {
    int t = blockIdx.x * blockDim.x + threadIdx.x;
    if (t < 2) d_bar[t] = 0u;
    if (t < 2 * 2 * HDIM) ((float*)d_hstate)[t] = 0.f;
}

// ---------------- SGEMM: C[M,N] = act(A[M,K] @ B[N,K]^T + bias[N]) ----------------
// 128x128 block, BK=16, 256 threads, 8x8 per thread. act: 0=none, 1=relu, 2=sigmoid
__global__ __launch_bounds__(256) void sgemm_kernel(
    const float* __restrict__ A, const float* __restrict__ B,
    const float* __restrict__ bias, float* __restrict__ C,
    int M, int N, int K, int act)
{
    __shared__ float As[16][128];
    __shared__ float Bs[16][128];
    int tid = threadIdx.x;
    int tx = tid % 16, ty = tid / 16;
    const float* Ablk = A + (size_t)blockIdx.y * 128 * K;
    const float* Bblk = B + (size_t)blockIdx.x * 128 * K;

    float acc[8][8];
#pragma unroll
    for (int i = 0; i < 8; i++)
#pragma unroll
        for (int j = 0; j < 8; j++) acc[i][j] = 0.f;

    for (int k0 = 0; k0 < K; k0 += 16) {
#pragma unroll
        for (int i = 0; i < 2; i++) {
            int idx = tid + i * 256;      // 0..511
            int r = idx >> 2;             // tile row 0..127
            int c4 = idx & 3;             // float4 within 16-wide k slab
            float4 va = *(const float4*)(Ablk + (size_t)r * K + k0 + c4 * 4);
            As[c4 * 4 + 0][r] = va.x; As[c4 * 4 + 1][r] = va.y;
            As[c4 * 4 + 2][r] = va.z; As[c4 * 4 + 3][r] = va.w;
            float4 vb = *(const float4*)(Bblk + (size_t)r * K + k0 + c4 * 4);
            Bs[c4 * 4 + 0][r] = vb.x; Bs[c4 * 4 + 1][r] = vb.y;
            Bs[c4 * 4 + 2][r] = vb.z; Bs[c4 * 4 + 3][r] = vb.w;
        }
        __syncthreads();
#pragma unroll
        for (int k = 0; k < 16; k++) {
            float4 a0 = *(const float4*)&As[k][ty * 8];
            float4 a1 = *(const float4*)&As[k][ty * 8 + 4];
            float4 b0 = *(const float4*)&Bs[k][tx * 8];
            float4 b1 = *(const float4*)&Bs[k][tx * 8 + 4];
            float ar[8] = {a0.x, a0.y, a0.z, a0.w, a1.x, a1.y, a1.z, a1.w};
            float br[8] = {b0.x, b0.y, b0.z, b0.w, b1.x, b1.y, b1.z, b1.w};
#pragma unroll
            for (int i = 0; i < 8; i++)
#pragma unroll
                for (int j = 0; j < 8; j++) acc[i][j] = fmaf(ar[i], br[j], acc[i][j]);
        }
        __syncthreads();
    }

    int nbase = blockIdx.x * 128 + tx * 8;
    int mbase = blockIdx.y * 128 + ty * 8;
#pragma unroll
    for (int i = 0; i < 8; i++) {
#pragma unroll
        for (int j = 0; j < 8; j++) {
            float v = acc[i][j];
            if (bias) v += bias[nbase + j];
            if (act == 1) v = fmaxf(v, 0.f);
            else if (act == 2) v = 1.f / (1.f + expf(-v));
            acc[i][j] = v;
        }
        float4* dst = (float4*)(C + (size_t)(mbase + i) * N + nbase);
        dst[0] = make_float4(acc[i][0], acc[i][1], acc[i][2], acc[i][3]);
        dst[1] = make_float4(acc[i][4], acc[i][5], acc[i][6], acc[i][7]);
    }
}

// ---------------- persistent bidirectional GRU recurrence ----------------
// 32 CTAs per direction (64 total, all co-resident), 384 threads each.
// Each CTA owns 16 output elements -> 48 dot products of length 512.
// Thread layout: chunk = tid/48 (8 chunks of 64 h-elems), gate = (tid%48)/16, jl = tid%16.
// w_hh slice lives in registers (16 float4 per thread).
#define DCTAS 32
#define OPC 16
#define RTH 384

__global__ __launch_bounds__(RTH, 1) void gru_kernel(
    const float* __restrict__ whh_f, const float* __restrict__ bhh_f,
    const float* __restrict__ whh_b, const float* __restrict__ bhh_b)
{
    int cta = blockIdx.x;
    int dir = (cta >= DCTAS) ? 1 : 0;
    int slice = cta - dir * DCTAS;
    const float* whh = dir ? whh_b : whh_f;
    const float* bhh = dir ? bhh_b : bhh_f;
    const float* gibase = d_gi[dir];
    unsigned int* bar = &d_bar[dir];

    int tid = threadIdx.x;
    int chunk = tid / 48;
    int t48 = tid - chunk * 48;
    int gate = t48 / OPC;
    int jl = t48 - gate * OPC;
    int jg = slice * OPC + jl;

    float4 w[16];
    {
        const float4* wr = (const float4*)(whh + (size_t)(gate * HDIM + jg) * HDIM + chunk * 64);
#pragma unroll
        for (int i = 0; i < 16; i++) w[i] = wr[i];
    }
    float myb = (tid < 48) ? bhh[gate * HDIM + jg] : 0.f;

    __shared__ float h_sh[HDIM];
    __shared__ float part[3][OPC][8];
    __shared__ float s_r[OPC], s_z[OPC], s_in[OPC], s_hn[OPC];

    for (int i = tid; i < HDIM; i += RTH) h_sh[i] = 0.f;
    __syncthreads();

    for (int s = 0; s < LSEQ; s++) {
        int t = dir ? (LSEQ - 1 - s) : s;
        float giv = 0.f;
        if (tid < 48) giv = __ldg(gibase + (size_t)t * 1536 + gate * HDIM + jg);

        // partial dot: h chunk (64) x register weights
        float acc = 0.f;
        const float4* h4 = ((const float4*)h_sh) + chunk * 16;
#pragma unroll
        for (int i = 0; i < 16; i++) {
            float4 hv = h4[i];
            acc = fmaf(w[i].x, hv.x, acc);
            acc = fmaf(w[i].y, hv.y, acc);
            acc = fmaf(w[i].z, hv.z, acc);
            acc = fmaf(w[i].w, hv.w, acc);
        }
        part[gate][jl][chunk] = acc;
        __syncthreads();

        if (tid < 48) {
            float sum = myb;
#pragma unroll
            for (int c = 0; c < 8; c++) sum += part[gate][jl][c];
            if (gate == 0) s_r[jl] = giv + sum;          // ir + hr (+b)
            else if (gate == 1) s_z[jl] = giv + sum;     // iz + hz (+b)
            else { s_in[jl] = giv; s_hn[jl] = sum; }     // inn ; hn(+b)
        }
        __syncthreads();

        if (tid < OPC) {
            float r = 1.f / (1.f + expf(-s_r[tid]));
            float z = 1.f / (1.f + expf(-s_z[tid]));
            float n = tanhf(s_in[tid] + r * s_hn[tid]);
            float hp = h_sh[slice * OPC + tid];
            float hnew = (1.f - z) * n + z * hp;
            __stcg(&d_hstate[dir][((s + 1) & 1) * HDIM + slice * OPC + tid], hnew);
            d_outcat[(size_t)t * 1024 + dir * HDIM + slice * OPC + tid] = hnew;
            __threadfence();
        }
        __syncthreads();

        if (tid == 0) {
            atomicAdd(bar, 1u);
            unsigned int target = (unsigned)(s + 1) * DCTAS;
            unsigned int v;
            do {
                asm volatile("ld.acquire.gpu.u32 %0, [%1];" : "=r"(v) : "l"(bar) : "memory");
            } while (v < target);
        }
        __syncthreads();

        if (s + 1 < LSEQ) {
            const float4* hg = (const float4*)&d_hstate[dir][((s + 1) & 1) * HDIM];
            for (int i = tid; i < HDIM / 4; i += RTH)
                ((float4*)h_sh)[i] = __ldcg(hg + i);
            __syncthreads();
        }
    }
}

// ---------------- KAN prep: cubic B-spline basis on efficient-kan extended grid ----------------
__device__ __forceinline__ void bspline8(float x, float* bs) {
    const float hstep = 2.0f / 5.0f;
    float g[12];
#pragma unroll
    for (int m = 0; m < 12; m++) g[m] = (float)(m - 3) * hstep - 1.0f;
    float b[11];
#pragma unroll
    for (int m = 0; m < 11; m++) b[m] = (x >= g[m] && x < g[m + 1]) ? 1.f : 0.f;
#pragma unroll
    for (int k = 1; k <= 3; k++) {
#pragma unroll
        for (int m = 0; m < 11 - k; m++) {
            b[m] = (x - g[m]) / (g[m + k] - g[m]) * b[m]
                 + (g[m + k + 1] - x) / (g[m + k + 1] - g[m + 1]) * b[m + 1];
        }
    }
#pragma unroll
    for (int m = 0; m < 8; m++) bs[m] = b[m];
}

// U[n] = [ silu(x[n,0..inw]) | bases(x[n,0])... ] width = 9*inw
__global__ void prep_U_kernel(const float* __restrict__ X, float* __restrict__ U, int inw) {
    int idx = blockIdx.x * blockDim.x + threadIdx.x;
    int total = LSEQ * inw;
    if (idx >= total) return;
    int n = idx / inw, i = idx - n * inw;
    float x = X[idx];
    int uw = inw * 9;
    U[(size_t)n * uw + i] = x / (1.f + expf(-x));
    float bs[8];
    bspline8(x, bs);
    float4* d4 = (float4*)(U + (size_t)n * uw + inw + (size_t)i * 8);
    d4[0] = make_float4(bs[0], bs[1], bs[2], bs[3]);
    d4[1] = make_float4(bs[4], bs[5], bs[6], bs[7]);
}

// V[o] = [ base_w[o,:] | spline_w[o,:,:]*scaler[o,:] ]
__global__ void prep_V_kernel(const float* __restrict__ bw, const float* __restrict__ sw,
                              const float* __restrict__ sc, float* __restrict__ V, int inw) {
    int idx = blockIdx.x * blockDim.x + threadIdx.x;
    int total = HDIM * inw;
    if (idx >= total) return;
    int o = idx / inw, i = idx - o * inw;
    int uw = inw * 9;
    V[(size_t)o * uw + i] = bw[idx];
    float s = sc[idx];
    const float* swp = sw + (size_t)idx * 8;
    float4* d4 = (float4*)(V + (size_t)o * uw + inw + (size_t)i * 8);
    d4[0] = make_float4(swp[0] * s, swp[1] * s, swp[2] * s, swp[3] * s);
    d4[1] = make_float4(swp[4] * s, swp[5] * s, swp[6] * s, swp[7] * s);
}

// ---------------- y[o] = sum_n a2[n,o] * p[n] ----------------
__global__ void final_kernel(const float* __restrict__ p, float* __restrict__ y) {
    __shared__ float red[256];
    int o = blockIdx.x * 64 + (threadIdx.x & 63);
    int part = threadIdx.x >> 6;
    float acc = 0.f;
    for (int n = part; n < LSEQ; n += 4)
        acc += d_a2[(size_t)n * HDIM + o] * p[n];
    red[threadIdx.x] = acc;
    __syncthreads();
    if (part == 0)
        y[o] = red[threadIdx.x] + red[threadIdx.x + 64]
             + red[threadIdx.x + 128] + red[threadIdx.x + 192];
}

// ---------------- launch ----------------
extern "C" void kernel_launch(void* const* d_in, const int* in_sizes, int n_in,
                              void* d_out, int out_size) {
    const float* h    = (const float*)d_in[0];
    const float* p    = (const float*)d_in[1];
    const float* wihf = (const float*)d_in[2];
    const float* whhf = (const float*)d_in[3];
    const float* bihf = (const float*)d_in[4];
    const float* bhhf = (const float*)d_in[5];
    const float* wihb = (const float*)d_in[6];
    const float* whhb = (const float*)d_in[7];
    const float* bihb = (const float*)d_in[8];
    const float* bhhb = (const float*)d_in[9];
    const float* bw1  = (const float*)d_in[10];
    const float* sw1  = (const float*)d_in[11];
    const float* sc1  = (const float*)d_in[12];
    const float* bw2  = (const float*)d_in[13];
    const float* sw2  = (const float*)d_in[14];
    const float* sc2  = (const float*)d_in[15];

    float* out = (float*)d_out;
    float* y  = out;           // (512,)
    float* a1 = out + 512;     // (4096, 512)

    float *gi0, *oc, *u1, *v1, *u2, *v2, *a2;
    cudaGetSymbolAddress((void**)&gi0, d_gi);
    cudaGetSymbolAddress((void**)&oc,  d_outcat);
    cudaGetSymbolAddress((void**)&u1,  d_U1);
    cudaGetSymbolAddress((void**)&v1,  d_V1);
    cudaGetSymbolAddress((void**)&u2,  d_U2);
    cudaGetSymbolAddress((void**)&v2,  d_V2);
    cudaGetSymbolAddress((void**)&a2,  d_a2);
    float* gi1 = gi0 + (size_t)LSEQ * 1536;

    init_kernel<<<2, 1024>>>();

    // input-gate GEMMs: gi = h @ w_ih^T + b_ih   (4096 x 1536, K=512)
    sgemm_kernel<<<dim3(1536 / 128, LSEQ / 128), 256>>>(h, wihf, bihf, gi0, LSEQ, 1536, 512, 0);
    sgemm_kernel<<<dim3(1536 / 128, LSEQ / 128), 256>>>(h, wihb, bihb, gi1, LSEQ, 1536, 512, 0);

    // persistent bidirectional recurrence
    gru_kernel<<<2 * DCTAS, RTH>>>(whhf, bhhf, whhb, bhhb);

    // KAN layer 1: a1 = relu(U1 @ V1^T), U1 = [silu | bases] of outcat (width 9216)
    prep_V_kernel<<<(HDIM * 1024 + 255) / 256, 256>>>(bw1, sw1, sc1, v1, 1024);
    prep_U_kernel<<<(LSEQ * 1024 + 255) / 256, 256>>>(oc, u1, 1024);
    sgemm_kernel<<<dim3(HDIM / 128, LSEQ / 128), 256>>>(u1, v1, nullptr, a1, LSEQ, HDIM, 9216, 1);

    // KAN layer 2: a2 = sigmoid(U2 @ V2^T), width 4608
    prep_V_kernel<<<(HDIM * 512 + 255) / 256, 256>>>(bw2, sw2, sc2, v2, 512);
    prep_U_kernel<<<(LSEQ * 512 + 255) / 256, 256>>>(a1, u2, 512);
    sgemm_kernel<<<dim3(HDIM / 128, LSEQ / 128), 256>>>(u2, v2, nullptr, a2, LSEQ, HDIM, 4608, 2);

    // y = a2^T @ p
    final_kernel<<<8, 256>>>(p, y);
}